// round 2
// baseline (speedup 1.0000x reference)
#include <cuda_runtime.h>
#include <math.h>

#define HID   2560
#define E_TOT 2048
#define KTOT  2688        // 2560 recurrent + 128 input cols
#define BATCH 64
#define TSTEPS 500
#define IN_DIM 128

// Static device scratch (no allocations allowed)
__device__ float g_W[HID * KTOT];          // fused effective weights [H, 2688]
__device__ float g_x[BATCH * HID];         // membrane state
__device__ float g_r[2][BATCH * HID];      // ping-pong rates

// ---------------------------------------------------------------------------
// Build W_eff = [ |W_rec| * rec_mask | |W_in| * in_mask ] once per run.
// Connectivity rule (verified against reference _build_masks):
//   col k excitatory (k<2048):  connected iff |area(h)-area(k)| <= 1, sign +1
//   col k inhibitory          :  connected iff  area(h)==area(k),     sign -1
//   diagonal removed; input cols only for area(h)==0, sign +1.
// ---------------------------------------------------------------------------
__global__ void build_weights_kernel(const float* __restrict__ W_rec,
                                     const float* __restrict__ W_in) {
    int idx = blockIdx.x * blockDim.x + threadIdx.x;
    if (idx >= HID * KTOT) return;
    int h = idx / KTOT;
    int k = idx - h * KTOT;
    int ah = (h < E_TOT) ? (h >> 9) : ((h - E_TOT) >> 7);
    float w = 0.0f;
    if (k < HID) {
        int  ak = (k < E_TOT) ? (k >> 9) : ((k - E_TOT) >> 7);
        bool ek = (k < E_TOT);
        int  d  = ah - ak; if (d < 0) d = -d;
        bool conn = ek ? (d <= 1) : (d == 0);
        if (h == k) conn = false;
        if (conn) w = fabsf(W_rec[h * HID + k]) * (ek ? 1.0f : -1.0f);
    } else {
        if (ah == 0) w = fabsf(W_in[h * IN_DIM + (k - HID)]);
    }
    g_W[idx] = w;
}

__global__ void init_state_kernel() {
    int idx = blockIdx.x * blockDim.x + threadIdx.x;
    if (idx < BATCH * HID) {
        g_x[idx]    = 0.0f;
        g_r[0][idx] = 0.0f;   // r0 = retanh(0) = 0
    }
}

// ---------------------------------------------------------------------------
// One RNN step: pre = r_t @ W_rec_eff^T + u_t @ W_in_eff^T + b
//               x  = 0.8*x + 0.2*pre ; r = tanh(relu(x))
// Block = 64(batch) x 32(h) output tile; 128 threads, 4x4 register frags.
// K loop only visits the (<=3) contiguous nonzero ranges for this h-tile.
// ---------------------------------------------------------------------------
__global__ __launch_bounds__(128) void step_kernel(
    const float* __restrict__ inputs,   // [T, 64, 128]
    int t,
    const float* __restrict__ b_rec,    // [H]
    float* __restrict__ rates_t,        // out + t*64*2560
    int par)                            // ping-pong parity
{
    __shared__ float As[64][33];   // [b][k] padded: conflict-free
    __shared__ float Bs[32][33];   // [k][h] padded: conflict-free

    const float* __restrict__ rin  = g_r[par];
    float*       __restrict__ rout = g_r[par ^ 1];

    const int tid = threadIdx.x;
    const int h0  = blockIdx.x * 32;
    const int a   = (h0 < E_TOT) ? (h0 >> 9) : ((h0 - E_TOT) >> 7);

    // nonzero K ranges for this tile (all 32-aligned, 32-multiple lengths)
    int r_lo[3], r_hi[3], nr = 0;
    {
        int lo = (a > 0 ? a - 1 : 0) * 512;
        int hi = ((a < 3 ? a + 1 : 3) + 1) * 512;
        r_lo[nr] = lo;               r_hi[nr] = hi;               nr++;   // E cols
        r_lo[nr] = E_TOT + a * 128;  r_hi[nr] = r_lo[nr] + 128;   nr++;   // I cols
        if (a == 0) { r_lo[nr] = HID; r_hi[nr] = KTOT; nr++; }            // input
    }

    float acc[4][4];
    #pragma unroll
    for (int i = 0; i < 4; i++)
        #pragma unroll
        for (int j = 0; j < 4; j++) acc[i][j] = 0.0f;

    const int hq = (tid & 7) << 2;   // h offset within tile: 0,4,...,28
    const int b0 = (tid >> 3) << 2;  // batch offset: 0,4,...,60
    const float* __restrict__ inp_t = inputs + (size_t)t * (BATCH * IN_DIM);

    for (int ri = 0; ri < nr; ri++) {
        const bool isin = (r_lo[ri] >= HID);
        for (int k0 = r_lo[ri]; k0 < r_hi[ri]; k0 += 32) {
            __syncthreads();
            // --- load A tile (64 x 32): 512 float4, coalesced over k ---
            #pragma unroll
            for (int rep = 0; rep < 4; rep++) {
                int f  = tid + 128 * rep;        // 0..511
                int b  = f >> 3;
                int kq = (f & 7) << 2;
                const float* src = isin
                    ? (inp_t + b * IN_DIM + (k0 - HID) + kq)
                    : (rin   + b * HID    +  k0        + kq);
                float4 v = *reinterpret_cast<const float4*>(src);
                As[b][kq + 0] = v.x; As[b][kq + 1] = v.y;
                As[b][kq + 2] = v.z; As[b][kq + 3] = v.w;
            }
            // --- load B tile (32h x 32k) transposed into [k][h] ---
            #pragma unroll
            for (int rep = 0; rep < 2; rep++) {
                int f  = tid + 128 * rep;        // 0..255
                int hh = f >> 3;
                int kq = (f & 7) << 2;
                float4 v = *reinterpret_cast<const float4*>(
                    &g_W[(size_t)(h0 + hh) * KTOT + k0 + kq]);
                Bs[kq + 0][hh] = v.x; Bs[kq + 1][hh] = v.y;
                Bs[kq + 2][hh] = v.z; Bs[kq + 3][hh] = v.w;
            }
            __syncthreads();
            // --- 4x4 outer-product accumulation ---
            #pragma unroll
            for (int kk = 0; kk < 32; kk++) {
                float av[4], bv[4];
                #pragma unroll
                for (int i = 0; i < 4; i++) av[i] = As[b0 + i][kk];
                #pragma unroll
                for (int j = 0; j < 4; j++) bv[j] = Bs[kk][hq + j];
                #pragma unroll
                for (int i = 0; i < 4; i++)
                    #pragma unroll
                    for (int j = 0; j < 4; j++)
                        acc[i][j] = fmaf(av[i], bv[j], acc[i][j]);
            }
        }
    }

    // --- epilogue: leaky integration + retanh, write state & output ---
    #pragma unroll
    for (int i = 0; i < 4; i++) {
        int b = b0 + i;
        #pragma unroll
        for (int j = 0; j < 4; j++) {
            int h   = h0 + hq + j;
            int idx = b * HID + h;
            float pre = acc[i][j] + b_rec[h];
            float xv  = g_x[idx];
            xv = 0.8f * xv + 0.2f * pre;
            g_x[idx] = xv;
            float r = (xv > 0.0f) ? tanhf(xv) : 0.0f;
            rout[idx]    = r;
            rates_t[idx] = r;
        }
    }
}

// ---------------------------------------------------------------------------
extern "C" void kernel_launch(void* const* d_in, const int* in_sizes, int n_in,
                              void* d_out, int out_size) {
    const float *inputs = nullptr, *W_rec = nullptr,
                *b_rec = nullptr,  *W_in  = nullptr;
    // identify inputs by unique element counts (defensive vs ordering)
    for (int i = 0; i < n_in; i++) {
        long n = (long)in_sizes[i];
        if      (n == (long)TSTEPS * BATCH * IN_DIM) inputs = (const float*)d_in[i];
        else if (n == (long)HID * HID)               W_rec  = (const float*)d_in[i];
        else if (n == (long)HID)                     b_rec  = (const float*)d_in[i];
        else if (n == (long)HID * IN_DIM)            W_in   = (const float*)d_in[i];
    }
    float* out = (float*)d_out;

    int nW = HID * KTOT;
    build_weights_kernel<<<(nW + 255) / 256, 256>>>(W_rec, W_in);
    init_state_kernel<<<(BATCH * HID + 255) / 256, 256>>>();

    for (int t = 0; t < TSTEPS; t++) {
        step_kernel<<<HID / 32, 128>>>(
            inputs, t, b_rec, out + (size_t)t * BATCH * HID, t & 1);
    }
}

// round 3
// speedup vs baseline: 1.0374x; 1.0374x over previous
#include <cuda_runtime.h>
#include <math.h>

#define HID    2560
#define E_TOT  2048
#define KTOT   2688        // 2560 recurrent + 128 input cols
#define BATCH  64
#define TSTEPS 500
#define IN_DIM 128
#define NTILE  40          // h-tiles of 64
#define SMAX   9
#define CHUNK  192         // K per split CTA (multiple of 32)
#define GRID_STEP 310      // 10 tiles/area * (7+9+9+6)

// Static device scratch (no allocations allowed)
__device__ float g_W[HID * KTOT];                 // fused effective weights [H, 2688]
__device__ float g_x[BATCH * HID];                // membrane state
__device__ float g_r[2][BATCH * HID];             // ping-pong rates
__device__ float g_partial[NTILE * SMAX * 4096];  // per-(tile,split) 64b x 64h partials
__device__ int   g_cnt[NTILE];                    // arrival counters

// ---------------------------------------------------------------------------
// Build W_eff = [ |W_rec| * rec_mask | |W_in| * in_mask ] once per run.
//   col k excitatory (k<2048):  connected iff |area(h)-area(k)| <= 1, sign +1
//   col k inhibitory          :  connected iff  area(h)==area(k),     sign -1
//   diagonal removed; input cols only for area(h)==0, sign +1.
// ---------------------------------------------------------------------------
__global__ void build_weights_kernel(const float* __restrict__ W_rec,
                                     const float* __restrict__ W_in) {
    int idx = blockIdx.x * blockDim.x + threadIdx.x;
    if (idx >= HID * KTOT) return;
    int h = idx / KTOT;
    int k = idx - h * KTOT;
    int ah = (h < E_TOT) ? (h >> 9) : ((h - E_TOT) >> 7);
    float w = 0.0f;
    if (k < HID) {
        int  ak = (k < E_TOT) ? (k >> 9) : ((k - E_TOT) >> 7);
        bool ek = (k < E_TOT);
        int  d  = ah - ak; if (d < 0) d = -d;
        bool conn = ek ? (d <= 1) : (d == 0);
        if (h == k) conn = false;
        if (conn) w = fabsf(W_rec[h * HID + k]) * (ek ? 1.0f : -1.0f);
    } else {
        if (ah == 0) w = fabsf(W_in[h * IN_DIM + (k - HID)]);
    }
    g_W[idx] = w;
}

__global__ void init_state_kernel() {
    int idx = blockIdx.x * blockDim.x + threadIdx.x;
    if (idx < BATCH * HID) {
        g_x[idx]    = 0.0f;
        g_r[0][idx] = 0.0f;   // r0 = retanh(0) = 0
    }
    if (idx < NTILE) g_cnt[idx] = 0;
}

// ---------------------------------------------------------------------------
// One RNN step, split-K. Each CTA: 64(batch) x 64(h) x CHUNK(K) partial GEMM.
// Last-arriving CTA of a tile reduces the S partials and applies
// x = 0.8x + 0.2(pre+b); r = tanh(relu(x)).
// ---------------------------------------------------------------------------
__global__ __launch_bounds__(128) void step_kernel(
    const float* __restrict__ inputs,   // [T, 64, 128]
    int t,
    const float* __restrict__ b_rec,    // [H]
    float* __restrict__ rates_t,        // out + t*64*2560
    int par)                            // ping-pong parity
{
    __shared__ float As[64][33];   // [b][k]
    __shared__ float Bs[64][33];   // [h][k]
    __shared__ int   sIsLast;

    const float* __restrict__ rin  = g_r[par];
    float*       __restrict__ rout = g_r[par ^ 1];

    const int tid = threadIdx.x;
    const int bid = blockIdx.x;

    // decode (area, tile-in-area, split)
    int a, local, Sa;
    if      (bid < 70)  { a = 0; local = bid;       Sa = 7; }
    else if (bid < 160) { a = 1; local = bid - 70;  Sa = 9; }
    else if (bid < 250) { a = 2; local = bid - 160; Sa = 9; }
    else                { a = 3; local = bid - 250; Sa = 6; }
    int ti = local / Sa;
    int s  = local - ti * Sa;
    int h0 = (ti < 8) ? (a * 512 + ti * 64) : (E_TOT + a * 128 + (ti - 8) * 64);
    int gtile = a * 10 + ti;

    // nonzero K ranges for this tile (virtual K -> actual col mapping)
    int lo0  = (a > 0 ? a - 1 : 0) * 512;
    int hi0  = ((a < 3 ? a + 1 : 3) + 1) * 512;
    int len0 = hi0 - lo0;                 // E columns
    int lo1  = E_TOT + a * 128;           // I columns (len 128)
    int Ktot = len0 + 128 + (a == 0 ? 128 : 0);
    int vstart = s * CHUNK;
    int vend   = min(vstart + CHUNK, Ktot);

    float acc[4][8];
    #pragma unroll
    for (int i = 0; i < 4; i++)
        #pragma unroll
        for (int j = 0; j < 8; j++) acc[i][j] = 0.0f;

    const int tg = tid >> 3;        // 0..15 : batch group (b = tg + 16*i)
    const int l8 = tid & 7;         // 0..7  : h lane (h = h0 + l8 + 8*j)
    const float* __restrict__ inp_t = inputs + (size_t)t * (BATCH * IN_DIM);

    for (int v0 = vstart; v0 < vend; v0 += 32) {
        int  k0;
        bool isin = false;
        if      (v0 < len0)       k0 = lo0 + v0;
        else if (v0 < len0 + 128) k0 = lo1 + (v0 - len0);
        else { k0 = HID + (v0 - len0 - 128); isin = true; }

        __syncthreads();
        // A tile (64b x 32k), 512 float4 coalesced over k
        #pragma unroll
        for (int rep = 0; rep < 4; rep++) {
            int f  = tid + 128 * rep;
            int b  = f >> 3;
            int kq = (f & 7) << 2;
            const float* src = isin
                ? (inp_t + b * IN_DIM + (k0 - HID) + kq)
                : (rin   + b * HID    +  k0        + kq);
            float4 v = *reinterpret_cast<const float4*>(src);
            As[b][kq + 0] = v.x; As[b][kq + 1] = v.y;
            As[b][kq + 2] = v.z; As[b][kq + 3] = v.w;
        }
        // B tile (64h x 32k), row-major, no transpose
        #pragma unroll
        for (int rep = 0; rep < 4; rep++) {
            int f  = tid + 128 * rep;
            int hh = f >> 3;
            int kq = (f & 7) << 2;
            float4 v = *reinterpret_cast<const float4*>(
                &g_W[(size_t)(h0 + hh) * KTOT + k0 + kq]);
            Bs[hh][kq + 0] = v.x; Bs[hh][kq + 1] = v.y;
            Bs[hh][kq + 2] = v.z; Bs[hh][kq + 3] = v.w;
        }
        __syncthreads();

        #pragma unroll
        for (int kk = 0; kk < 32; kk++) {
            float av[4], bv[8];
            #pragma unroll
            for (int i = 0; i < 4; i++) av[i] = As[tg + 16 * i][kk];
            #pragma unroll
            for (int j = 0; j < 8; j++) bv[j] = Bs[l8 + 8 * j][kk];
            #pragma unroll
            for (int i = 0; i < 4; i++)
                #pragma unroll
                for (int j = 0; j < 8; j++)
                    acc[i][j] = fmaf(av[i], bv[j], acc[i][j]);
        }
    }

    // write partial [64b x 64h]
    float* pp = &g_partial[(size_t)(gtile * SMAX + s) * 4096];
    #pragma unroll
    for (int i = 0; i < 4; i++)
        #pragma unroll
        for (int j = 0; j < 8; j++)
            pp[(tg + 16 * i) * 64 + (l8 + 8 * j)] = acc[i][j];

    __threadfence();
    __syncthreads();
    if (tid == 0) {
        int old = atomicAdd(&g_cnt[gtile], 1);
        sIsLast = (old == Sa * (t + 1) - 1);
    }
    __syncthreads();
    if (!sIsLast) return;
    __threadfence();   // acquire: make all splits' partials visible

    // epilogue: sum partials (fixed order -> deterministic), integrate, retanh
    const float* pbase = &g_partial[(size_t)gtile * SMAX * 4096];
    for (int e = tid; e < 4096; e += 128) {
        float sum = 0.0f;
        for (int s2 = 0; s2 < Sa; s2++)
            sum += pbase[s2 * 4096 + e];
        int b  = e >> 6;
        int hh = e & 63;
        int h  = h0 + hh;
        int idx = b * HID + h;
        float pre = sum + b_rec[h];
        float xv  = g_x[idx];
        xv = 0.8f * xv + 0.2f * pre;
        g_x[idx] = xv;
        float r = (xv > 0.0f) ? tanhf(xv) : 0.0f;
        rout[idx]    = r;
        rates_t[idx] = r;
    }
}

// ---------------------------------------------------------------------------
extern "C" void kernel_launch(void* const* d_in, const int* in_sizes, int n_in,
                              void* d_out, int out_size) {
    const float *inputs = nullptr, *W_rec = nullptr,
                *b_rec = nullptr,  *W_in  = nullptr;
    for (int i = 0; i < n_in; i++) {
        long n = (long)in_sizes[i];
        if      (n == (long)TSTEPS * BATCH * IN_DIM) inputs = (const float*)d_in[i];
        else if (n == (long)HID * HID)               W_rec  = (const float*)d_in[i];
        else if (n == (long)HID)                     b_rec  = (const float*)d_in[i];
        else if (n == (long)HID * IN_DIM)            W_in   = (const float*)d_in[i];
    }
    float* out = (float*)d_out;

    int nW = HID * KTOT;
    build_weights_kernel<<<(nW + 255) / 256, 256>>>(W_rec, W_in);
    init_state_kernel<<<(BATCH * HID + 255) / 256, 256>>>();

    for (int t = 0; t < TSTEPS; t++) {
        step_kernel<<<GRID_STEP, 128>>>(
            inputs, t, b_rec, out + (size_t)t * BATCH * HID, t & 1);
    }
}

// round 6
// speedup vs baseline: 3.2147x; 3.0989x over previous
#include <cuda_runtime.h>
#include <math.h>
#include <stdint.h>

#define HID    2560
#define BATCH  64
#define TSTEPS 500
#define IN_DIM 128
#define GRID   80
#define STAGE_B 13824                       // W 64*144B + r 32*144B
#define ROFF    9216
#define MRG_OFF (4*STAGE_B)                 // 55296
#define MRG_STR 8704                        // 64*34*4
#define SMEM_TOTAL (MRG_OFF + 4*MRG_STR)    // 90112

// static scratch (allocations forbidden)
__device__ float g_Wb[1800*2048];             // blocked tf32 W_eff: [blk][64h][32k]
__device__ float g_intf[TSTEPS*BATCH*IN_DIM]; // tf32-rounded inputs
__device__ float g_r[2][BATCH*HID];           // tf32-rounded rates ping-pong [b][h]
__device__ int   g_bar;

// ---------------------------------------------------------------------------
// Builders. Connectivity (validated rounds 2-3 at rel_err 1e-8):
//  E col k(<2048): |area(h)-area(k)|<=1, +|w|;  I col: same area, -|w|;
//  diagonal removed; input cols only for area-0 rows, +|w_in|.
// Per 64-h tile: nE E-slabs (areas a-1..a+1), 4 I-slabs, (a==0) 4 input slabs.
// ---------------------------------------------------------------------------
__global__ void build_W(const float* __restrict__ W_rec, const float* __restrict__ W_in) {
    int idx = blockIdx.x*blockDim.x + threadIdx.x;
    if (idx >= 1800*2048) return;
    int blk = idx >> 11, e = idx & 2047;
    int hl = e >> 5, cc = e & 31;
    int a    = (blk<400)?0:(blk<920)?1:(blk<1440)?2:3;
    int base = (a==0)?0:(a==1)?400:(a==2)?920:1440;
    int nE   = (a==1||a==2)?48:32;
    int nblk = nE + 4 + ((a==0)?4:0);
    int ti = (blk - base)/nblk;
    int i  = (blk - base) - ti*nblk;
    int hbase = (ti<8) ? a*512 + ti*64 : 2048 + a*128 + (ti-8)*64;
    int h = hbase + hl;
    float v = 0.f;
    if (i < nE) {
        int k = (a>0?a-1:0)*512 + i*32 + cc;
        if (k != h) v = fabsf(W_rec[(size_t)h*HID + k]);
    } else if (i < nE+4) {
        int k = 2048 + a*128 + (i-nE)*32 + cc;
        if (k != h) v = -fabsf(W_rec[(size_t)h*HID + k]);
    } else {
        int kin = (i-nE-4)*32 + cc;
        v = fabsf(W_in[(size_t)h*IN_DIM + kin]);
    }
    uint32_t o; asm("cvt.rna.tf32.f32 %0, %1;" : "=r"(o) : "f"(v));
    g_Wb[idx] = __uint_as_float(o);
}

__global__ void build_in(const float* __restrict__ in) {
    int idx = blockIdx.x*blockDim.x + threadIdx.x;
    if (idx >= TSTEPS*BATCH*IN_DIM) return;
    uint32_t o; asm("cvt.rna.tf32.f32 %0, %1;" : "=r"(o) : "f"(in[idx]));
    g_intf[idx] = __uint_as_float(o);
}

__global__ void init_k() {
    int idx = blockIdx.x*blockDim.x + threadIdx.x;
    if (idx < BATCH*HID) g_r[0][idx] = 0.f;   // r0 = retanh(0) = 0
    if (idx == 0) g_bar = 0;
}

// ---------------------------------------------------------------------------
__device__ __forceinline__ void cp16(uint32_t d, const void* s) {
    asm volatile("cp.async.cg.shared.global [%0], [%1], 16;" :: "r"(d), "l"(s) : "memory");
}
__device__ __forceinline__ void cpcommit() { asm volatile("cp.async.commit_group;" ::: "memory"); }
__device__ __forceinline__ void cpwait(int n) {
    if (n >= 2)      asm volatile("cp.async.wait_group 2;" ::: "memory");
    else if (n == 1) asm volatile("cp.async.wait_group 1;" ::: "memory");
    else             asm volatile("cp.async.wait_group 0;" ::: "memory");
}

// ---------------------------------------------------------------------------
// Persistent kernel: 80 CTAs (40 h-tiles x 2 batch halves) x 128 threads.
// ---------------------------------------------------------------------------
__global__ void __launch_bounds__(128, 1) rnn_kernel(const float* __restrict__ b_rec,
                                                     float* __restrict__ out) {
    extern __shared__ char sm[];
    uint32_t sb;
    asm("{ .reg .u64 t; cvta.to.shared.u64 t, %1; cvt.u32.u64 %0, t; }" : "=r"(sb) : "l"(sm));
    const int tid = threadIdx.x, wid = tid >> 5, lane = tid & 31;
    const int g = lane >> 2, cq = lane & 3;
    const int cta = blockIdx.x, tau = cta >> 1, bh = (cta & 1) << 5;
    const int a = tau/10, ti = tau - 10*a;
    const int hbase = (ti<8) ? a*512 + ti*64 : 2048 + a*128 + (ti-8)*64;
    const int nE    = (a==1||a==2)?48:32;
    const int nblk  = nE + 4 + ((a==0)?4:0);
    const int kE0   = (a>0?a-1:0)*512;
    const int kI0   = 2048 + a*128;
    const int baseA = (a==0)?0:(a==1)?400:(a==2)?920:1440;
    const int blkbase = baseA + ti*nblk;
    const float bias = b_rec[hbase + (tid & 63)];
    const int ko = wid*8;                 // warp's k8 slice within a 32-k slab

    float x[16];
    #pragma unroll
    for (int i = 0; i < 16; i++) x[i] = 0.f;

    for (int t = 0; t < TSTEPS; t++) {
        const float* __restrict__ rin  = g_r[t & 1];
        float*       __restrict__ rout = g_r[(t & 1) ^ 1];
        const float* __restrict__ inp  = g_intf + (size_t)t * (BATCH*IN_DIM);

        // prologue: issue slabs 0..2
        for (int s = 0; s < 3; s++) {
            uint32_t st = sb + (uint32_t)(s & 3)*STAGE_B;
            const float* wsrc = g_Wb + (size_t)(blkbase + s)*2048;
            #pragma unroll
            for (int j2 = 0; j2 < 4; j2++) {
                int f = tid + 128*j2;
                cp16(st + (uint32_t)(f>>3)*144 + (f&7)*16, wsrc + f*4);
            }
            const float* rsrc; int rstr, k0;
            if (s < nE)        { rsrc = rin; rstr = HID;    k0 = kE0 + 32*s; }
            else if (s < nE+4) { rsrc = rin; rstr = HID;    k0 = kI0 + 32*(s-nE); }
            else               { rsrc = inp; rstr = IN_DIM; k0 = 32*(s-nE-4); }
            #pragma unroll
            for (int j2 = 0; j2 < 2; j2++) {
                int f = tid + 128*j2;
                cp16(st + ROFF + (uint32_t)(f>>3)*144 + (f&7)*16,
                     rsrc + (size_t)(bh + (f>>3))*rstr + k0 + (f&7)*4);
            }
            cpcommit();
        }

        float acc[4][4][4];
        #pragma unroll
        for (int i = 0; i < 4; i++)
            #pragma unroll
            for (int j = 0; j < 4; j++)
                #pragma unroll
                for (int k = 0; k < 4; k++) acc[i][j][k] = 0.f;

        for (int s = 0; s < nblk; s++) {
            int ahead = nblk - 1 - s; if (ahead > 2) ahead = 2;
            cpwait(ahead);
            __syncthreads();
            if (s + 3 < nblk) {
                int s3 = s + 3;
                uint32_t st = sb + (uint32_t)(s3 & 3)*STAGE_B;
                const float* wsrc = g_Wb + (size_t)(blkbase + s3)*2048;
                #pragma unroll
                for (int j2 = 0; j2 < 4; j2++) {
                    int f = tid + 128*j2;
                    cp16(st + (uint32_t)(f>>3)*144 + (f&7)*16, wsrc + f*4);
                }
                const float* rsrc; int rstr, k0;
                if (s3 < nE)        { rsrc = rin; rstr = HID;    k0 = kE0 + 32*s3; }
                else if (s3 < nE+4) { rsrc = rin; rstr = HID;    k0 = kI0 + 32*(s3-nE); }
                else                { rsrc = inp; rstr = IN_DIM; k0 = 32*(s3-nE-4); }
                #pragma unroll
                for (int j2 = 0; j2 < 2; j2++) {
                    int f = tid + 128*j2;
                    cp16(st + ROFF + (uint32_t)(f>>3)*144 + (f&7)*16,
                         rsrc + (size_t)(bh + (f>>3))*rstr + k0 + (f&7)*4);
                }
                cpcommit();
            }
            // compute slab s: this warp's 8-k slice over the whole 64x32 tile
            {
                const char* st = sm + (size_t)(s & 3)*STAGE_B;
                uint32_t A[4][4], B[4][2];
                #pragma unroll
                for (int i = 0; i < 4; i++) {
                    const char* r0 = st + (16*i + g)*144;
                    const char* r8 = st + (16*i + g + 8)*144;
                    A[i][0] = __float_as_uint(*(const float*)(r0 + (ko+cq)*4));
                    A[i][1] = __float_as_uint(*(const float*)(r8 + (ko+cq)*4));
                    A[i][2] = __float_as_uint(*(const float*)(r0 + (ko+cq+4)*4));
                    A[i][3] = __float_as_uint(*(const float*)(r8 + (ko+cq+4)*4));
                }
                #pragma unroll
                for (int j = 0; j < 4; j++) {
                    const char* rp = st + ROFF + (8*j + g)*144;
                    B[j][0] = __float_as_uint(*(const float*)(rp + (ko+cq)*4));
                    B[j][1] = __float_as_uint(*(const float*)(rp + (ko+cq+4)*4));
                }
                #pragma unroll
                for (int i = 0; i < 4; i++)
                    #pragma unroll
                    for (int j = 0; j < 4; j++)
                        asm volatile(
                            "mma.sync.aligned.m16n8k8.row.col.f32.tf32.tf32.f32 "
                            "{%0,%1,%2,%3},{%4,%5,%6,%7},{%8,%9},{%0,%1,%2,%3};"
                            : "+f"(acc[i][j][0]), "+f"(acc[i][j][1]),
                              "+f"(acc[i][j][2]), "+f"(acc[i][j][3])
                            : "r"(A[i][0]), "r"(A[i][1]), "r"(A[i][2]), "r"(A[i][3]),
                              "r"(B[j][0]), "r"(B[j][1]));
            }
        }

        // merge 4 k-split partials via smem
        {
            char* mb = sm + MRG_OFF + wid*MRG_STR;
            #pragma unroll
            for (int i = 0; i < 4; i++)
                #pragma unroll
                for (int j = 0; j < 4; j++) {
                    *(float2*)(mb + ((16*i+g  )*34 + 8*j + 2*cq)*4) =
                        make_float2(acc[i][j][0], acc[i][j][1]);
                    *(float2*)(mb + ((16*i+g+8)*34 + 8*j + 2*cq)*4) =
                        make_float2(acc[i][j][2], acc[i][j][3]);
                }
        }
        __syncthreads();

        // epilogue: thread owns h = tid&63, batches b = bh + (tid>>6) + 2*ii
        const int hh = tid & 63;
        const int bq = tid >> 6;
        #pragma unroll
        for (int ii = 0; ii < 16; ii++) {
            int bl = bq + 2*ii;
            uint32_t off = ((uint32_t)hh*34 + bl)*4;
            float sum = *(const float*)(sm + MRG_OFF + off)
                      + *(const float*)(sm + MRG_OFF +   MRG_STR + off)
                      + *(const float*)(sm + MRG_OFF + 2*MRG_STR + off)
                      + *(const float*)(sm + MRG_OFF + 3*MRG_STR + off);
            float pre = sum + bias;
            float xv  = 0.8f*x[ii] + 0.2f*pre;
            x[ii] = xv;
            float r = (xv > 0.f) ? tanhf(xv) : 0.f;
            size_t gi = (size_t)(bh + bl)*HID + hbase + hh;
            out[(size_t)t*(BATCH*HID) + gi] = r;
            uint32_t o; asm("cvt.rna.tf32.f32 %0, %1;" : "=r"(o) : "f"(r));
            rout[gi] = __uint_as_float(o);
        }

        // grid barrier (monotonic counter; 80 CTAs all co-resident)
        __threadfence();
        __syncthreads();
        if (tid == 0) {
            atomicAdd(&g_bar, 1);
            while (*((volatile int*)&g_bar) < GRID*(t+1)) { }
        }
        __syncthreads();
        __threadfence();
    }
}

// ---------------------------------------------------------------------------
extern "C" void kernel_launch(void* const* d_in, const int* in_sizes, int n_in,
                              void* d_out, int out_size) {
    const float *inputs = nullptr, *W_rec = nullptr,
                *b_rec = nullptr,  *W_in  = nullptr;
    for (int i = 0; i < n_in; i++) {
        long n = (long)in_sizes[i];
        if      (n == (long)TSTEPS*BATCH*IN_DIM) inputs = (const float*)d_in[i];
        else if (n == (long)HID*HID)             W_rec  = (const float*)d_in[i];
        else if (n == (long)HID)                 b_rec  = (const float*)d_in[i];
        else if (n == (long)HID*IN_DIM)          W_in   = (const float*)d_in[i];
    }
    float* out = (float*)d_out;

    cudaFuncSetAttribute(rnn_kernel, cudaFuncAttributeMaxDynamicSharedMemorySize, SMEM_TOTAL);

    build_W <<<(1800*2048 + 255)/256, 256>>>(W_rec, W_in);
    build_in<<<(TSTEPS*BATCH*IN_DIM + 255)/256, 256>>>(inputs);
    init_k  <<<(BATCH*HID + 255)/256, 256>>>();
    rnn_kernel<<<GRID, 128, SMEM_TOTAL>>>(b_rec, out);
}